// round 7
// baseline (speedup 1.0000x reference)
#include <cuda_runtime.h>
#include <cstdint>

#define EPSF 1e-6f
#define L2E  1.44269504088896340736f

constexpr int SI = 3000;
constexpr int SJ = 3000;
constexpr int NLINKS = 500000;
constexpr int BT = 256;
constexpr int GATHER_BLOCKS = (SI + BT - 1) / BT;   // 12

constexpr int NBLK = 444;                 // 148 SMs * 3 resident blocks -> one wave
constexpr int LINK_CHUNK = 2000;
constexpr int NLT = NLINKS / LINK_CHUNK;  // 250 link items (exact)
constexpr int IT = 4;                     // i's per block-term tile (R3-proven codegen)
constexpr int JHALF = SJ / 2;             // 1500
constexpr int NBT = (SI / IT) * 2;        // 750 i-groups x 2 j-halves = 1500 tiles
constexpr int NW = NLT + NBT;             // 1750 work items

// ---------------- scratch ----------------
__device__ float4 g_zi0[SI], g_zi1[SI];      // gathered zi rows, EPS pre-added
__device__ float  g_bL[SI];                  // beta[si]*log2(e)
__device__ float4 g_zj0[SJ], g_zj1[SJ];      // gathered zj rows, NEGATED
__device__ float  g_gL[SJ];                  // gamma[sj]*log2(e)
__device__ float  g_part_block[NBT];
__device__ float  g_part_links[NLT];
__device__ int    g_ticket;

typedef unsigned long long u64;

__device__ __forceinline__ u64 ADD2(u64 a, u64 b) {
    u64 r; asm("add.rn.f32x2 %0,%1,%2;" : "=l"(r) : "l"(a), "l"(b)); return r;
}
__device__ __forceinline__ u64 MUL2(u64 a, u64 b) {
    u64 r; asm("mul.rn.f32x2 %0,%1,%2;" : "=l"(r) : "l"(a), "l"(b)); return r;
}
__device__ __forceinline__ u64 FMA2(u64 a, u64 b, u64 c) {
    u64 r; asm("fma.rn.f32x2 %0,%1,%2,%3;" : "=l"(r) : "l"(a), "l"(b), "l"(c)); return r;
}
__device__ __forceinline__ float LOHI_ADD(u64 v) {
    unsigned lo, hi;
    asm("mov.b64 {%0,%1}, %2;" : "=r"(lo), "=r"(hi) : "l"(v));
    return __uint_as_float(lo) + __uint_as_float(hi);
}

__device__ __forceinline__ float warp_sum(float v) {
    #pragma unroll
    for (int o = 16; o > 0; o >>= 1) v += __shfl_xor_sync(0xffffffffu, v, o);
    return v;
}
// Block-level sum; result valid in thread 0. Safe under repeated calls:
// the leading __syncthreads protects the shared buffer from prior readers.
__device__ __forceinline__ float block_sum(float v) {
    __shared__ float w[BT / 32];
    __syncthreads();
    v = warp_sum(v);
    if ((threadIdx.x & 31) == 0) w[threadIdx.x >> 5] = v;
    __syncthreads();
    if (threadIdx.x < BT / 32) {
        v = w[threadIdx.x];
        #pragma unroll
        for (int o = BT / 64; o > 0; o >>= 1) v += __shfl_xor_sync(0xffu, v, o);
    }
    return v;
}

// ================= kernel 1: gather + prescale (tiny) =================
__global__ __launch_bounds__(BT) void k1(const float* __restrict__ zi,
                                         const float* __restrict__ zj,
                                         const float* __restrict__ beta,
                                         const float* __restrict__ gamma,
                                         const int*   __restrict__ si,
                                         const int*   __restrict__ sj) {
    const int t = blockIdx.x * BT + threadIdx.x;
    if (t == 0) g_ticket = 0;
    if (t < SI) {
        const int i = si[t];
        float4 a0 = __ldg((const float4*)&zi[i * 8]);
        float4 a1 = __ldg((const float4*)&zi[i * 8 + 4]);
        a0.x += EPSF; a0.y += EPSF; a0.z += EPSF; a0.w += EPSF;
        a1.x += EPSF; a1.y += EPSF; a1.z += EPSF; a1.w += EPSF;
        g_zi0[t] = a0; g_zi1[t] = a1;
        g_bL[t] = beta[i] * L2E;
    }
    if (t < SJ) {
        const int j = sj[t];
        float4 b0 = __ldg((const float4*)&zj[j * 8]);
        float4 b1 = __ldg((const float4*)&zj[j * 8 + 4]);
        b0.x = -b0.x; b0.y = -b0.y; b0.z = -b0.z; b0.w = -b0.w;
        b1.x = -b1.x; b1.y = -b1.y; b1.z = -b1.z; b1.w = -b1.w;
        g_zj0[t] = b0; g_zj1[t] = b1;
        g_gL[t] = gamma[j] * L2E;
    }
}

// ================= kernel 2: one-wave static interleaved schedule =================
__global__ __launch_bounds__(BT) void k2(const float* __restrict__ zi,
                                         const float* __restrict__ zj,
                                         const float* __restrict__ beta,
                                         const float* __restrict__ gamma,
                                         const int*   __restrict__ li,
                                         const int*   __restrict__ lj,
                                         float* __restrict__ out) {
    const ulonglong2* __restrict__ ZJ0 = (const ulonglong2*)g_zj0;
    const ulonglong2* __restrict__ ZJ1 = (const ulonglong2*)g_zj1;

    for (int w = blockIdx.x; w < NW; w += NBLK) {
        if (w < NLT) {
            // ---- link chunk w: edges [w*LINK_CHUNK, (w+1)*LINK_CHUNK) ----
            const int start = w * LINK_CHUNK;
            const int end   = start + LINK_CHUNK;
            float acc = 0.0f;
            for (int e = start + threadIdx.x; e < end; e += BT) {
                const int i = li[e];
                const int j = lj[e];
                const float4 a0 = __ldg((const float4*)&zi[i * 8]);
                const float4 a1 = __ldg((const float4*)&zi[i * 8 + 4]);
                const float4 b0 = __ldg((const float4*)&zj[j * 8]);
                const float4 b1 = __ldg((const float4*)&zj[j * 8 + 4]);
                float d0 = a0.x - b0.x + EPSF, d1 = a0.y - b0.y + EPSF;
                float d2 = a0.z - b0.z + EPSF, d3 = a0.w - b0.w + EPSF;
                float d4 = a1.x - b1.x + EPSF, d5 = a1.y - b1.y + EPSF;
                float d6 = a1.z - b1.z + EPSF, d7 = a1.w - b1.w + EPSF;
                float s = d0 * d0;
                s = fmaf(d1, d1, s); s = fmaf(d2, d2, s); s = fmaf(d3, d3, s);
                s = fmaf(d4, d4, s); s = fmaf(d5, d5, s); s = fmaf(d6, d6, s);
                s = fmaf(d7, d7, s);
                const float u = rsqrtf(s);
                acc += __ldg(&beta[i]) + __ldg(&gamma[j]) - s * u;
            }
            const float tot = block_sum(acc);
            if (threadIdx.x == 0) g_part_links[w] = tot;
        } else {
            // ---- block-term tile: IT i's x half of j ----
            const int t     = w - NLT;           // 0..NBT-1
            const int ib    = (t >> 1) * IT;     // i-group base
            const int jbase = (t & 1) * JHALF;   // j-half base
            const int jend  = jbase + JHALF;

            u64 A01[IT], A23[IT], A45[IT], A67[IT];
            float bL[IT];
            #pragma unroll
            for (int u = 0; u < IT; u++) {
                const ulonglong2 p0 = *(const ulonglong2*)&g_zi0[ib + u];
                const ulonglong2 p1 = *(const ulonglong2*)&g_zi1[ib + u];
                A01[u] = p0.x; A23[u] = p0.y; A45[u] = p1.x; A67[u] = p1.y;
                bL[u] = g_bL[ib + u];
            }
            float acc[IT];
            #pragma unroll
            for (int u = 0; u < IT; u++) acc[u] = 0.0f;

            for (int j = jbase + threadIdx.x; j < jend; j += BT) {
                const ulonglong2 q0 = ZJ0[j];      // packed (-zj)
                const ulonglong2 q1 = ZJ1[j];
                const float gL = g_gL[j];
                #pragma unroll
                for (int u = 0; u < IT; u++) {
                    u64 d01 = ADD2(A01[u], q0.x);
                    u64 d23 = ADD2(A23[u], q0.y);
                    u64 d45 = ADD2(A45[u], q1.x);
                    u64 d67 = ADD2(A67[u], q1.y);
                    u64 sp  = MUL2(d01, d01);
                    sp = FMA2(d23, d23, sp);
                    sp = FMA2(d45, d45, sp);
                    sp = FMA2(d67, d67, sp);
                    const float s = LOHI_ADD(sp);
                    const float r = rsqrtf(s);                      // MUFU.RSQ
                    const float tt = fmaf(s * r, -L2E, bL[u] + gL); // log2-domain
                    float e;
                    asm("ex2.approx.f32 %0, %1;" : "=f"(e) : "f"(tt));
                    acc[u] += e;
                }
            }
            const float tot = block_sum(acc[0] + acc[1] + acc[2] + acc[3]);
            if (threadIdx.x == 0) g_part_block[t] = tot;
        }
    }

    // ---- last-finishing block performs the deterministic final reduction ----
    __shared__ int isLast;
    __threadfence();                                   // release our partials
    if (threadIdx.x == 0) isLast = (atomicAdd(&g_ticket, 1) == NBLK - 1);
    __syncthreads();
    if (!isLast) return;
    __threadfence();                                   // acquire others' partials

    __shared__ double redB[BT], redL[BT];
    double sb = 0.0, sl = 0.0;
    for (int k = threadIdx.x; k < NBT; k += BT) sb += (double)g_part_block[k];
    for (int k = threadIdx.x; k < NLT; k += BT) sl += (double)g_part_links[k];
    redB[threadIdx.x] = sb;
    redL[threadIdx.x] = sl;
    __syncthreads();
    #pragma unroll
    for (int s2 = BT / 2; s2 > 0; s2 >>= 1) {
        if (threadIdx.x < s2) {
            redB[threadIdx.x] += redB[threadIdx.x + s2];
            redL[threadIdx.x] += redL[threadIdx.x + s2];
        }
        __syncthreads();
    }
    if (threadIdx.x == 0) out[0] = (float)(redL[0] - redB[0]);
}

extern "C" void kernel_launch(void* const* d_in, const int* in_sizes, int n_in,
                              void* d_out, int out_size) {
    const float* latent_zi = (const float*)d_in[0];
    const float* latent_zj = (const float*)d_in[1];
    const float* beta      = (const float*)d_in[2];
    const float* gamma     = (const float*)d_in[3];
    const int*   si        = (const int*)  d_in[4];
    const int*   sj        = (const int*)  d_in[5];
    const int*   li        = (const int*)  d_in[6];
    const int*   lj        = (const int*)  d_in[7];
    float* out = (float*)d_out;

    k1<<<GATHER_BLOCKS, BT>>>(latent_zi, latent_zj, beta, gamma, si, sj);
    k2<<<NBLK, BT>>>(latent_zi, latent_zj, beta, gamma, li, lj, out);
}

// round 8
// speedup vs baseline: 1.1043x; 1.1043x over previous
#include <cuda_runtime.h>
#include <cstdint>

#define EPSF 1e-6f
#define L2E  1.44269504088896340736f

constexpr int SI = 3000;
constexpr int SJ = 3000;
constexpr int NLINKS = 500000;
constexpr int BT = 256;
constexpr int GATHER_BLOCKS = (SI + BT - 1) / BT;   // 12
constexpr int IT = 4;                               // i's per block-term block
constexpr int NBI = SI / IT;                        // 750
constexpr int K2_LINK = 296;                        // link blocks (after block tiles)
constexpr int K2_TOTAL = NBI + K2_LINK;

// ---------------- scratch ----------------
__device__ float4 g_zi0[SI], g_zi1[SI];      // gathered zi rows, EPS pre-added
__device__ float  g_na[SI];                  // ||zi+eps||^2
__device__ float  g_bL[SI];                  // beta[si]*log2(e)
__device__ float4 g_q0[SJ], g_q1[SJ];        // gathered -2*zj rows
__device__ float2 g_nbgL[SJ];                // { ||zj||^2, gamma[sj]*log2(e) }
__device__ float  g_part_block[NBI];
__device__ float  g_part_links[K2_LINK];
__device__ int    g_ticket;

typedef unsigned long long u64;

__device__ __forceinline__ u64 MUL2(u64 a, u64 b) {
    u64 r; asm("mul.rn.f32x2 %0,%1,%2;" : "=l"(r) : "l"(a), "l"(b)); return r;
}
__device__ __forceinline__ u64 FMA2(u64 a, u64 b, u64 c) {
    u64 r; asm("fma.rn.f32x2 %0,%1,%2,%3;" : "=l"(r) : "l"(a), "l"(b), "l"(c)); return r;
}
__device__ __forceinline__ float LOHI_ADD(u64 v) {
    unsigned lo, hi;
    asm("mov.b64 {%0,%1}, %2;" : "=r"(lo), "=r"(hi) : "l"(v));
    return __uint_as_float(lo) + __uint_as_float(hi);
}

__device__ __forceinline__ float warp_sum(float v) {
    #pragma unroll
    for (int o = 16; o > 0; o >>= 1) v += __shfl_xor_sync(0xffffffffu, v, o);
    return v;
}
__device__ __forceinline__ float block_sum(float v) {
    __shared__ float w[BT / 32];
    v = warp_sum(v);
    if ((threadIdx.x & 31) == 0) w[threadIdx.x >> 5] = v;
    __syncthreads();
    if (threadIdx.x < BT / 32) {
        v = w[threadIdx.x];
        #pragma unroll
        for (int o = BT / 64; o > 0; o >>= 1) v += __shfl_xor_sync(0xffu, v, o);
    }
    return v;
}

// ================= kernel 1: gather + prescale + norms =================
__global__ __launch_bounds__(BT) void k1(const float* __restrict__ zi,
                                         const float* __restrict__ zj,
                                         const float* __restrict__ beta,
                                         const float* __restrict__ gamma,
                                         const int*   __restrict__ si,
                                         const int*   __restrict__ sj) {
    const int t = blockIdx.x * BT + threadIdx.x;
    if (t == 0) g_ticket = 0;
    if (t < SI) {
        const int i = si[t];
        float4 a0 = __ldg((const float4*)&zi[i * 8]);
        float4 a1 = __ldg((const float4*)&zi[i * 8 + 4]);
        a0.x += EPSF; a0.y += EPSF; a0.z += EPSF; a0.w += EPSF;
        a1.x += EPSF; a1.y += EPSF; a1.z += EPSF; a1.w += EPSF;
        g_zi0[t] = a0; g_zi1[t] = a1;
        float na = a0.x * a0.x;
        na = fmaf(a0.y, a0.y, na); na = fmaf(a0.z, a0.z, na); na = fmaf(a0.w, a0.w, na);
        na = fmaf(a1.x, a1.x, na); na = fmaf(a1.y, a1.y, na); na = fmaf(a1.z, a1.z, na);
        na = fmaf(a1.w, a1.w, na);
        g_na[t] = na;
        g_bL[t] = beta[i] * L2E;
    }
    if (t < SJ) {
        const int j = sj[t];
        const float4 b0 = __ldg((const float4*)&zj[j * 8]);
        const float4 b1 = __ldg((const float4*)&zj[j * 8 + 4]);
        float nb = b0.x * b0.x;
        nb = fmaf(b0.y, b0.y, nb); nb = fmaf(b0.z, b0.z, nb); nb = fmaf(b0.w, b0.w, nb);
        nb = fmaf(b1.x, b1.x, nb); nb = fmaf(b1.y, b1.y, nb); nb = fmaf(b1.z, b1.z, nb);
        nb = fmaf(b1.w, b1.w, nb);
        float4 q0, q1;
        q0.x = -2.0f * b0.x; q0.y = -2.0f * b0.y; q0.z = -2.0f * b0.z; q0.w = -2.0f * b0.w;
        q1.x = -2.0f * b1.x; q1.y = -2.0f * b1.y; q1.z = -2.0f * b1.z; q1.w = -2.0f * b1.w;
        g_q0[t] = q0; g_q1[t] = q1;
        g_nbgL[t] = make_float2(nb, gamma[j] * L2E);
    }
}

// ================= kernel 2: block tiles first, then link chunks =================
__global__ __launch_bounds__(BT) void k2(const float* __restrict__ zi,
                                         const float* __restrict__ zj,
                                         const float* __restrict__ beta,
                                         const float* __restrict__ gamma,
                                         const int*   __restrict__ li,
                                         const int*   __restrict__ lj,
                                         float* __restrict__ out) {
    if (blockIdx.x < NBI) {
        // ---- block-term tile: IT i's x all j (norm-trick f32x2 dot core) ----
        const int ib = blockIdx.x * IT;
        const ulonglong2* __restrict__ Q0 = (const ulonglong2*)g_q0;
        const ulonglong2* __restrict__ Q1 = (const ulonglong2*)g_q1;

        u64 A01[IT], A23[IT], A45[IT], A67[IT];
        float na[IT], bL[IT];
        #pragma unroll
        for (int u = 0; u < IT; u++) {
            const ulonglong2 p0 = *(const ulonglong2*)&g_zi0[ib + u];
            const ulonglong2 p1 = *(const ulonglong2*)&g_zi1[ib + u];
            A01[u] = p0.x; A23[u] = p0.y; A45[u] = p1.x; A67[u] = p1.y;
            na[u] = g_na[ib + u];
            bL[u] = g_bL[ib + u];
        }
        float acc[IT];
        #pragma unroll
        for (int u = 0; u < IT; u++) acc[u] = 0.0f;

        for (int j = threadIdx.x; j < SJ; j += BT) {
            const ulonglong2 q0 = Q0[j];          // packed (-2 zj)
            const ulonglong2 q1 = Q1[j];
            const float2 ng = g_nbgL[j];          // { nb, gL }
            #pragma unroll
            for (int u = 0; u < IT; u++) {
                u64 sp = MUL2(A01[u], q0.x);      // a * (-2b) accumulating dot
                sp = FMA2(A23[u], q0.y, sp);
                sp = FMA2(A45[u], q1.x, sp);
                sp = FMA2(A67[u], q1.y, sp);
                float s = LOHI_ADD(sp) + (na[u] + ng.x);   // ||a||^2+||b||^2-2ab
                s = fmaxf(s, 1e-12f);                      // cancellation guard
                const float r = rsqrtf(s);                 // MUFU.RSQ
                const float t = fmaf(s * r, -L2E, bL[u] + ng.y);
                float e;
                asm("ex2.approx.f32 %0, %1;" : "=f"(e) : "f"(t));  // MUFU.EX2
                acc[u] += e;
            }
        }
        const float tot = block_sum(acc[0] + acc[1] + acc[2] + acc[3]);
        if (threadIdx.x == 0) g_part_block[blockIdx.x] = tot;
    } else {
        // ---- link term (unchanged from R3; exact subtraction form) ----
        const int b = blockIdx.x - NBI;
        const int stride = K2_LINK * BT;
        float acc = 0.0f;
        for (int e = b * BT + threadIdx.x; e < NLINKS; e += stride) {
            const int i = li[e];
            const int j = lj[e];
            const float4 a0 = __ldg((const float4*)&zi[i * 8]);
            const float4 a1 = __ldg((const float4*)&zi[i * 8 + 4]);
            const float4 b0 = __ldg((const float4*)&zj[j * 8]);
            const float4 b1 = __ldg((const float4*)&zj[j * 8 + 4]);
            float d0 = a0.x - b0.x + EPSF, d1 = a0.y - b0.y + EPSF;
            float d2 = a0.z - b0.z + EPSF, d3 = a0.w - b0.w + EPSF;
            float d4 = a1.x - b1.x + EPSF, d5 = a1.y - b1.y + EPSF;
            float d6 = a1.z - b1.z + EPSF, d7 = a1.w - b1.w + EPSF;
            float s = d0 * d0;
            s = fmaf(d1, d1, s); s = fmaf(d2, d2, s); s = fmaf(d3, d3, s);
            s = fmaf(d4, d4, s); s = fmaf(d5, d5, s); s = fmaf(d6, d6, s);
            s = fmaf(d7, d7, s);
            const float u = rsqrtf(s);
            acc += __ldg(&beta[i]) + __ldg(&gamma[j]) - s * u;
        }
        const float tot = block_sum(acc);
        if (threadIdx.x == 0) g_part_links[b] = tot;
    }

    // ---- last-finishing block performs the deterministic final reduction ----
    __shared__ int isLast;
    __threadfence();                                   // release our partials
    if (threadIdx.x == 0) isLast = (atomicAdd(&g_ticket, 1) == K2_TOTAL - 1);
    __syncthreads();
    if (!isLast) return;
    __threadfence();                                   // acquire others' partials

    __shared__ double redB[BT], redL[BT];
    double sb = 0.0, sl = 0.0;
    for (int k = threadIdx.x; k < NBI; k += BT)     sb += (double)g_part_block[k];
    for (int k = threadIdx.x; k < K2_LINK; k += BT) sl += (double)g_part_links[k];
    redB[threadIdx.x] = sb;
    redL[threadIdx.x] = sl;
    __syncthreads();
    #pragma unroll
    for (int s2 = BT / 2; s2 > 0; s2 >>= 1) {
        if (threadIdx.x < s2) {
            redB[threadIdx.x] += redB[threadIdx.x + s2];
            redL[threadIdx.x] += redL[threadIdx.x + s2];
        }
        __syncthreads();
    }
    if (threadIdx.x == 0) out[0] = (float)(redL[0] - redB[0]);
}

extern "C" void kernel_launch(void* const* d_in, const int* in_sizes, int n_in,
                              void* d_out, int out_size) {
    const float* latent_zi = (const float*)d_in[0];
    const float* latent_zj = (const float*)d_in[1];
    const float* beta      = (const float*)d_in[2];
    const float* gamma     = (const float*)d_in[3];
    const int*   si        = (const int*)  d_in[4];
    const int*   sj        = (const int*)  d_in[5];
    const int*   li        = (const int*)  d_in[6];
    const int*   lj        = (const int*)  d_in[7];
    float* out = (float*)d_out;

    k1<<<GATHER_BLOCKS, BT>>>(latent_zi, latent_zj, beta, gamma, si, sj);
    k2<<<K2_TOTAL, BT>>>(latent_zi, latent_zj, beta, gamma, li, lj, out);
}

// round 9
// speedup vs baseline: 1.1832x; 1.0714x over previous
#include <cuda_runtime.h>
#include <cstdint>

#define EPSF 1e-6f
#define L2E  1.44269504088896340736f

constexpr int SI = 3000;
constexpr int SJ = 3000;
constexpr int NLINKS = 500000;
constexpr int BT = 256;
constexpr int GATHER_BLOCKS = (SI + BT - 1) / BT;   // 12
constexpr int IT = 4;                               // i's per block-term block
constexpr int NBI = SI / IT;                        // 750
constexpr int K2_LINK = 296;                        // link blocks (first in grid)
constexpr int K2_TOTAL = K2_LINK + NBI;

// ---------------- scratch ----------------
__device__ float4 g_zi0[SI], g_zi1[SI];      // gathered zi rows, EPS pre-added
__device__ float  g_bL[SI];                  // beta[si]*log2(e)
__device__ float4 g_zj0[SJ], g_zj1[SJ];      // gathered zj rows
__device__ float  g_gL[SJ];                  // gamma[sj]*log2(e)
__device__ float  g_part_block[NBI];
__device__ float  g_part_links[K2_LINK];
__device__ int    g_ticket;

__device__ __forceinline__ float warp_sum(float v) {
    #pragma unroll
    for (int o = 16; o > 0; o >>= 1) v += __shfl_xor_sync(0xffffffffu, v, o);
    return v;
}
__device__ __forceinline__ float block_sum(float v) {
    __shared__ float w[BT / 32];
    v = warp_sum(v);
    if ((threadIdx.x & 31) == 0) w[threadIdx.x >> 5] = v;
    __syncthreads();
    if (threadIdx.x < BT / 32) {
        v = w[threadIdx.x];
        #pragma unroll
        for (int o = BT / 64; o > 0; o >>= 1) v += __shfl_xor_sync(0xffu, v, o);
    }
    return v;
}

// ================= kernel 1: gather + prescale =================
__global__ __launch_bounds__(BT) void k1(const float* __restrict__ zi,
                                         const float* __restrict__ zj,
                                         const float* __restrict__ beta,
                                         const float* __restrict__ gamma,
                                         const int*   __restrict__ si,
                                         const int*   __restrict__ sj) {
    const int t = blockIdx.x * BT + threadIdx.x;
    if (t == 0) g_ticket = 0;
    if (t < SI) {
        const int i = si[t];
        float4 a0 = __ldg((const float4*)&zi[i * 8]);
        float4 a1 = __ldg((const float4*)&zi[i * 8 + 4]);
        a0.x += EPSF; a0.y += EPSF; a0.z += EPSF; a0.w += EPSF;
        a1.x += EPSF; a1.y += EPSF; a1.z += EPSF; a1.w += EPSF;
        g_zi0[t] = a0; g_zi1[t] = a1;
        g_bL[t] = beta[i] * L2E;
    }
    if (t < SJ) {
        const int j = sj[t];
        g_zj0[t] = __ldg((const float4*)&zj[j * 8]);
        g_zj1[t] = __ldg((const float4*)&zj[j * 8 + 4]);
        g_gL[t] = gamma[j] * L2E;
    }
}

// ================= kernel 2: links (first) + block term + final reduce =================
__global__ __launch_bounds__(BT, 4) void k2(const float* __restrict__ zi,
                                            const float* __restrict__ zj,
                                            const float* __restrict__ beta,
                                            const float* __restrict__ gamma,
                                            const int*   __restrict__ li,
                                            const int*   __restrict__ lj,
                                            float* __restrict__ out) {
    if (blockIdx.x < K2_LINK) {
        // ---- link term (memory-latency bound) ----
        const int b = blockIdx.x;
        const int stride = K2_LINK * BT;
        float acc = 0.0f;
        for (int e = b * BT + threadIdx.x; e < NLINKS; e += stride) {
            const int i = li[e];
            const int j = lj[e];
            const float4 a0 = __ldg((const float4*)&zi[i * 8]);
            const float4 a1 = __ldg((const float4*)&zi[i * 8 + 4]);
            const float4 b0 = __ldg((const float4*)&zj[j * 8]);
            const float4 b1 = __ldg((const float4*)&zj[j * 8 + 4]);
            float d0 = a0.x - b0.x + EPSF, d1 = a0.y - b0.y + EPSF;
            float d2 = a0.z - b0.z + EPSF, d3 = a0.w - b0.w + EPSF;
            float d4 = a1.x - b1.x + EPSF, d5 = a1.y - b1.y + EPSF;
            float d6 = a1.z - b1.z + EPSF, d7 = a1.w - b1.w + EPSF;
            float s = d0 * d0;
            s = fmaf(d1, d1, s); s = fmaf(d2, d2, s); s = fmaf(d3, d3, s);
            s = fmaf(d4, d4, s); s = fmaf(d5, d5, s); s = fmaf(d6, d6, s);
            s = fmaf(d7, d7, s);
            const float u = rsqrtf(s);
            acc += __ldg(&beta[i]) + __ldg(&gamma[j]) - s * u;
        }
        const float tot = block_sum(acc);
        if (threadIdx.x == 0) g_part_links[b] = tot;
    } else {
        // ---- sampled block term: IT i's x all j, scalar core (R2-proven) ----
        const int ib = (blockIdx.x - K2_LINK) * IT;

        float4 a0[IT], a1[IT];
        float  bL[IT];
        #pragma unroll
        for (int u = 0; u < IT; u++) {
            a0[u] = g_zi0[ib + u];
            a1[u] = g_zi1[ib + u];
            bL[u] = g_bL[ib + u];
        }
        float acc[IT];
        #pragma unroll
        for (int u = 0; u < IT; u++) acc[u] = 0.0f;

        for (int j = threadIdx.x; j < SJ; j += BT) {
            const float4 b0 = g_zj0[j];
            const float4 b1 = g_zj1[j];
            const float  gL = g_gL[j];
            #pragma unroll
            for (int u = 0; u < IT; u++) {
                float d0 = a0[u].x - b0.x, d1 = a0[u].y - b0.y;
                float d2 = a0[u].z - b0.z, d3 = a0[u].w - b0.w;
                float d4 = a1[u].x - b1.x, d5 = a1[u].y - b1.y;
                float d6 = a1[u].z - b1.z, d7 = a1[u].w - b1.w;
                float s = d0 * d0;
                s = fmaf(d1, d1, s); s = fmaf(d2, d2, s); s = fmaf(d3, d3, s);
                s = fmaf(d4, d4, s); s = fmaf(d5, d5, s); s = fmaf(d6, d6, s);
                s = fmaf(d7, d7, s);
                s = fmaxf(s, 1e-35f);
                const float r = rsqrtf(s);                       // MUFU.RSQ
                const float t = fmaf(s * r, -L2E, bL[u] + gL);   // log2 domain
                float e;
                asm("ex2.approx.f32 %0, %1;" : "=f"(e) : "f"(t)); // MUFU.EX2
                acc[u] += e;
            }
        }
        const float tot = block_sum(acc[0] + acc[1] + acc[2] + acc[3]);
        if (threadIdx.x == 0) g_part_block[blockIdx.x - K2_LINK] = tot;
    }

    // ---- last-finishing block performs the deterministic final reduction ----
    __shared__ int isLast;
    __threadfence();                                   // release our partials
    if (threadIdx.x == 0) isLast = (atomicAdd(&g_ticket, 1) == K2_TOTAL - 1);
    __syncthreads();
    if (!isLast) return;
    __threadfence();                                   // acquire others' partials

    __shared__ double redB[BT], redL[BT];
    double sb = 0.0, sl = 0.0;
    for (int k = threadIdx.x; k < NBI; k += BT)     sb += (double)g_part_block[k];
    for (int k = threadIdx.x; k < K2_LINK; k += BT) sl += (double)g_part_links[k];
    redB[threadIdx.x] = sb;
    redL[threadIdx.x] = sl;
    __syncthreads();
    #pragma unroll
    for (int s2 = BT / 2; s2 > 0; s2 >>= 1) {
        if (threadIdx.x < s2) {
            redB[threadIdx.x] += redB[threadIdx.x + s2];
            redL[threadIdx.x] += redL[threadIdx.x + s2];
        }
        __syncthreads();
    }
    if (threadIdx.x == 0) out[0] = (float)(redL[0] - redB[0]);
}

extern "C" void kernel_launch(void* const* d_in, const int* in_sizes, int n_in,
                              void* d_out, int out_size) {
    const float* latent_zi = (const float*)d_in[0];
    const float* latent_zj = (const float*)d_in[1];
    const float* beta      = (const float*)d_in[2];
    const float* gamma     = (const float*)d_in[3];
    const int*   si        = (const int*)  d_in[4];
    const int*   sj        = (const int*)  d_in[5];
    const int*   li        = (const int*)  d_in[6];
    const int*   lj        = (const int*)  d_in[7];
    float* out = (float*)d_out;

    k1<<<GATHER_BLOCKS, BT>>>(latent_zi, latent_zj, beta, gamma, si, sj);
    k2<<<K2_TOTAL, BT>>>(latent_zi, latent_zj, beta, gamma, li, lj, out);
}

// round 11
// speedup vs baseline: 1.3051x; 1.1030x over previous
#include <cuda_runtime.h>
#include <cstdint>

#define EPSF 1e-6f
#define L2E  1.44269504088896340736f

constexpr int SI = 3000;
constexpr int SJ = 3000;
constexpr int NLINKS = 500000;
constexpr int BT = 256;
constexpr int GATHER_BLOCKS = (SI + BT - 1) / BT;   // 12
constexpr int IT = 4;                               // i's per block-term block
constexpr int NBI = SI / IT;                        // 750
constexpr int K2_LINK = 296;                        // link blocks first (R3-proven layout)
constexpr int K2_TOTAL = K2_LINK + NBI;

// ---------------- device scratch (allocation-free) ----------------
__device__ float4 g_zi0[SI], g_zi1[SI];      // gathered zi rows, EPS pre-added
__device__ float  g_na[SI];                  // ||zi+eps||^2
__device__ float  g_bL[SI];                  // beta[si]*log2(e)
__device__ float4 g_q0[SJ], g_q1[SJ];        // gathered -2*zj rows
__device__ float2 g_nbgL[SJ];                // { ||zj||^2, gamma[sj]*log2(e) }
__device__ float  g_part_block[NBI];
__device__ float  g_part_links[K2_LINK];
__device__ int    g_ticket;

__device__ __forceinline__ float warp_sum(float v) {
    #pragma unroll
    for (int o = 16; o > 0; o >>= 1) v += __shfl_xor_sync(0xffffffffu, v, o);
    return v;
}
__device__ __forceinline__ float block_sum(float v) {
    __shared__ float w[BT / 32];
    v = warp_sum(v);
    if ((threadIdx.x & 31) == 0) w[threadIdx.x >> 5] = v;
    __syncthreads();
    if (threadIdx.x < BT / 32) {
        v = w[threadIdx.x];
        #pragma unroll
        for (int o = BT / 64; o > 0; o >>= 1) v += __shfl_xor_sync(0xffu, v, o);
    }
    return v;
}

// ================= kernel 1: gather + prescale + norms =================
__global__ __launch_bounds__(BT) void k1(const float* __restrict__ zi,
                                         const float* __restrict__ zj,
                                         const float* __restrict__ beta,
                                         const float* __restrict__ gamma,
                                         const int*   __restrict__ si,
                                         const int*   __restrict__ sj) {
    const int t = blockIdx.x * BT + threadIdx.x;
    if (t == 0) g_ticket = 0;
    if (t < SI) {
        const int i = si[t];
        float4 a0 = __ldg((const float4*)&zi[i * 8]);
        float4 a1 = __ldg((const float4*)&zi[i * 8 + 4]);
        a0.x += EPSF; a0.y += EPSF; a0.z += EPSF; a0.w += EPSF;
        a1.x += EPSF; a1.y += EPSF; a1.z += EPSF; a1.w += EPSF;
        g_zi0[t] = a0; g_zi1[t] = a1;
        float na = a0.x * a0.x;
        na = fmaf(a0.y, a0.y, na); na = fmaf(a0.z, a0.z, na); na = fmaf(a0.w, a0.w, na);
        na = fmaf(a1.x, a1.x, na); na = fmaf(a1.y, a1.y, na); na = fmaf(a1.z, a1.z, na);
        na = fmaf(a1.w, a1.w, na);
        g_na[t] = na;
        g_bL[t] = beta[i] * L2E;
    }
    if (t < SJ) {
        const int j = sj[t];
        const float4 b0 = __ldg((const float4*)&zj[j * 8]);
        const float4 b1 = __ldg((const float4*)&zj[j * 8 + 4]);
        float nb = b0.x * b0.x;
        nb = fmaf(b0.y, b0.y, nb); nb = fmaf(b0.z, b0.z, nb); nb = fmaf(b0.w, b0.w, nb);
        nb = fmaf(b1.x, b1.x, nb); nb = fmaf(b1.y, b1.y, nb); nb = fmaf(b1.z, b1.z, nb);
        nb = fmaf(b1.w, b1.w, nb);
        float4 q0, q1;
        q0.x = -2.0f * b0.x; q0.y = -2.0f * b0.y; q0.z = -2.0f * b0.z; q0.w = -2.0f * b0.w;
        q1.x = -2.0f * b1.x; q1.y = -2.0f * b1.y; q1.z = -2.0f * b1.z; q1.w = -2.0f * b1.w;
        g_q0[t] = q0; g_q1[t] = q1;
        g_nbgL[t] = make_float2(nb, gamma[j] * L2E);
    }
}

// ====== kernel 2: links (first) + block term (scalar norm-trick) + final reduce ======
__global__ __launch_bounds__(BT) void k2(const float* __restrict__ zi,
                                         const float* __restrict__ zj,
                                         const float* __restrict__ beta,
                                         const float* __restrict__ gamma,
                                         const int*   __restrict__ li,
                                         const int*   __restrict__ lj,
                                         float* __restrict__ out) {
    if (blockIdx.x < K2_LINK) {
        // ---- link term (memory-latency bound; exact subtraction form) ----
        const int b = blockIdx.x;
        const int stride = K2_LINK * BT;
        float acc = 0.0f;
        for (int e = b * BT + threadIdx.x; e < NLINKS; e += stride) {
            const int i = li[e];
            const int j = lj[e];
            const float4 a0 = __ldg((const float4*)&zi[i * 8]);
            const float4 a1 = __ldg((const float4*)&zi[i * 8 + 4]);
            const float4 b0 = __ldg((const float4*)&zj[j * 8]);
            const float4 b1 = __ldg((const float4*)&zj[j * 8 + 4]);
            float d0 = a0.x - b0.x + EPSF, d1 = a0.y - b0.y + EPSF;
            float d2 = a0.z - b0.z + EPSF, d3 = a0.w - b0.w + EPSF;
            float d4 = a1.x - b1.x + EPSF, d5 = a1.y - b1.y + EPSF;
            float d6 = a1.z - b1.z + EPSF, d7 = a1.w - b1.w + EPSF;
            float s = d0 * d0;
            s = fmaf(d1, d1, s); s = fmaf(d2, d2, s); s = fmaf(d3, d3, s);
            s = fmaf(d4, d4, s); s = fmaf(d5, d5, s); s = fmaf(d6, d6, s);
            s = fmaf(d7, d7, s);
            const float u = rsqrtf(s);
            acc += __ldg(&beta[i]) + __ldg(&gamma[j]) - s * u;
        }
        const float tot = block_sum(acc);
        if (threadIdx.x == 0) g_part_links[b] = tot;
    } else {
        // ---- sampled block term: IT i's x all j, scalar norm-trick dot core ----
        const int ib = (blockIdx.x - K2_LINK) * IT;

        float4 A0[IT], A1[IT];
        float  na[IT];
        float  bL[IT];
        #pragma unroll
        for (int u = 0; u < IT; u++) {
            A0[u] = g_zi0[ib + u];
            A1[u] = g_zi1[ib + u];
            na[u] = g_na[ib + u];
            bL[u] = g_bL[ib + u];
        }
        float acc[IT];
        #pragma unroll
        for (int u = 0; u < IT; u++) acc[u] = 0.0f;

        for (int j = threadIdx.x; j < SJ; j += BT) {
            const float4 q0 = g_q0[j];            // -2*zj
            const float4 q1 = g_q1[j];
            const float2 ng = g_nbgL[j];          // { nb, gL }
            #pragma unroll
            for (int u = 0; u < IT; u++) {
                // s = (na + nb) + a.(-2b) : single 8-deep FFMA chain, 4-way ILP over u
                float s = fmaf(A0[u].x, q0.x, na[u] + ng.x);
                s = fmaf(A0[u].y, q0.y, s);
                s = fmaf(A0[u].z, q0.z, s);
                s = fmaf(A0[u].w, q0.w, s);
                s = fmaf(A1[u].x, q1.x, s);
                s = fmaf(A1[u].y, q1.y, s);
                s = fmaf(A1[u].z, q1.z, s);
                s = fmaf(A1[u].w, q1.w, s);
                s = fmaxf(s, 1e-12f);                            // cancellation guard
                const float r = rsqrtf(s);                       // MUFU.RSQ
                const float t = fmaf(s * r, -L2E, bL[u] + ng.y); // log2 domain
                float e;
                asm("ex2.approx.f32 %0, %1;" : "=f"(e) : "f"(t)); // MUFU.EX2
                acc[u] += e;
            }
        }
        const float tot = block_sum(acc[0] + acc[1] + acc[2] + acc[3]);
        if (threadIdx.x == 0) g_part_block[blockIdx.x - K2_LINK] = tot;
    }

    // ---- last-finishing block performs the deterministic final reduction ----
    __shared__ int isLast;
    __threadfence();                                   // release our partials
    if (threadIdx.x == 0) isLast = (atomicAdd(&g_ticket, 1) == K2_TOTAL - 1);
    __syncthreads();
    if (!isLast) return;
    __threadfence();                                   // acquire others' partials

    __shared__ double redB[BT], redL[BT];
    double sb = 0.0, sl = 0.0;
    for (int k = threadIdx.x; k < NBI; k += BT)     sb += (double)g_part_block[k];
    for (int k = threadIdx.x; k < K2_LINK; k += BT) sl += (double)g_part_links[k];
    redB[threadIdx.x] = sb;
    redL[threadIdx.x] = sl;
    __syncthreads();
    #pragma unroll
    for (int s2 = BT / 2; s2 > 0; s2 >>= 1) {
        if (threadIdx.x < s2) {
            redB[threadIdx.x] += redB[threadIdx.x + s2];
            redL[threadIdx.x] += redL[threadIdx.x + s2];
        }
        __syncthreads();
    }
    if (threadIdx.x == 0) out[0] = (float)(redL[0] - redB[0]);
}

extern "C" void kernel_launch(void* const* d_in, const int* in_sizes, int n_in,
                              void* d_out, int out_size) {
    const float* latent_zi = (const float*)d_in[0];
    const float* latent_zj = (const float*)d_in[1];
    const float* beta      = (const float*)d_in[2];
    const float* gamma     = (const float*)d_in[3];
    const int*   si        = (const int*)  d_in[4];
    const int*   sj        = (const int*)  d_in[5];
    const int*   li        = (const int*)  d_in[6];
    const int*   lj        = (const int*)  d_in[7];
    float* out = (float*)d_out;

    k1<<<GATHER_BLOCKS, BT>>>(latent_zi, latent_zj, beta, gamma, si, sj);
    k2<<<K2_TOTAL, BT>>>(latent_zi, latent_zj, beta, gamma, li, lj, out);
}